// round 11
// baseline (speedup 1.0000x reference)
#include <cuda_runtime.h>
#include <cuda_bf16.h>
#include <cstdint>

// out[t, :] = weight[words[t], :] * mask[words[t]]
// words: (16384,) int32, weight: (50257, 768) f32, mask: (50257,) f32
//
// R6: persistent CTAs + double-buffered pipeline. Profile showed weight reads
// are already L2-resident (DRAM ~= output writeback only) and nothing above
// 41% utilized -> latency/spread bound. Each CTA processes several 4-token
// tiles; while tile i is multiplied+stored, tile i+1's index/mask/gather
// loads are already in flight, so gather latency is exposed only once per
// CTA instead of once per tile. Thread c owns float4 column c (coalesced).

static constexpr int DIM   = 768;
static constexpr int VEC   = 4;               // float4
static constexpr int THREADS = DIM / VEC;     // 192
static constexpr int TOK   = 4;               // tokens per tile
static constexpr int ROWF4 = DIM / VEC;       // 192 float4 per row

__global__ __launch_bounds__(THREADS)
void embedding_dropout_pipe(const int* __restrict__ words,
                            const float* __restrict__ weight,
                            const float* __restrict__ mask,
                            float* __restrict__ out,
                            int ntiles)
{
    const int c    = threadIdx.x;
    const int grid = gridDim.x;
    const float4* w4 = reinterpret_cast<const float4*>(weight);
    const int4*   wi = reinterpret_cast<const int4*>(words);

    int t = blockIdx.x;
    if (t >= ntiles) return;

    // ---- prologue: tile t into buffer A ----
    int4 ia = __ldg(&wi[t]);
    float ma0 = __ldg(&mask[ia.x]), ma1 = __ldg(&mask[ia.y]);
    float ma2 = __ldg(&mask[ia.z]), ma3 = __ldg(&mask[ia.w]);
    float4 a0 = __ldg(w4 + (size_t)ia.x * ROWF4 + c);
    float4 a1 = __ldg(w4 + (size_t)ia.y * ROWF4 + c);
    float4 a2 = __ldg(w4 + (size_t)ia.z * ROWF4 + c);
    float4 a3 = __ldg(w4 + (size_t)ia.w * ROWF4 + c);

    for (;;) {
        const int tn = t + grid;
        const bool has_next = (tn < ntiles);

        // ---- issue next tile's loads (buffer B) before consuming A ----
        float mb0 = 0.f, mb1 = 0.f, mb2 = 0.f, mb3 = 0.f;
        float4 b0, b1, b2, b3;
        if (has_next) {
            int4 ib = __ldg(&wi[tn]);
            mb0 = __ldg(&mask[ib.x]); mb1 = __ldg(&mask[ib.y]);
            mb2 = __ldg(&mask[ib.z]); mb3 = __ldg(&mask[ib.w]);
            b0 = __ldg(w4 + (size_t)ib.x * ROWF4 + c);
            b1 = __ldg(w4 + (size_t)ib.y * ROWF4 + c);
            b2 = __ldg(w4 + (size_t)ib.z * ROWF4 + c);
            b3 = __ldg(w4 + (size_t)ib.w * ROWF4 + c);
        }

        // ---- consume A: scale + coalesced stores ----
        float4* dst = reinterpret_cast<float4*>(out) + (size_t)t * TOK * ROWF4 + c;
        float4 s;
        s = a0; s.x *= ma0; s.y *= ma0; s.z *= ma0; s.w *= ma0; dst[0 * ROWF4] = s;
        s = a1; s.x *= ma1; s.y *= ma1; s.z *= ma1; s.w *= ma1; dst[1 * ROWF4] = s;
        s = a2; s.x *= ma2; s.y *= ma2; s.z *= ma2; s.w *= ma2; dst[2 * ROWF4] = s;
        s = a3; s.x *= ma3; s.y *= ma3; s.z *= ma3; s.w *= ma3; dst[3 * ROWF4] = s;

        if (!has_next) break;

        // rotate B -> A
        a0 = b0; a1 = b1; a2 = b2; a3 = b3;
        ma0 = mb0; ma1 = mb1; ma2 = mb2; ma3 = mb3;
        t = tn;
    }
}

// Tail: one token per CTA (n_tokens % 4 != 0 only).
__global__ __launch_bounds__(THREADS)
void embedding_dropout_k1(const int* __restrict__ words,
                          const float* __restrict__ weight,
                          const float* __restrict__ mask,
                          float* __restrict__ out,
                          int t_base, int n_tokens)
{
    const int t = t_base + blockIdx.x;
    if (t >= n_tokens) return;
    const int row = __ldg(&words[t]);
    const float m = __ldg(&mask[row]);
    const float4* src = reinterpret_cast<const float4*>(weight) + (size_t)row * ROWF4;
    float4 v = __ldg(&src[threadIdx.x]);
    v.x *= m; v.y *= m; v.z *= m; v.w *= m;
    reinterpret_cast<float4*>(out)[(size_t)t * ROWF4 + threadIdx.x] = v;
}

extern "C" void kernel_launch(void* const* d_in, const int* in_sizes, int n_in,
                              void* d_out, int out_size)
{
    const int*   words  = (const int*)d_in[0];
    const float* weight = (const float*)d_in[1];
    const float* mask   = (const float*)d_in[2];
    float*       out    = (float*)d_out;

    const int n_tokens = in_sizes[0];          // 16384
    const int ntiles   = n_tokens / TOK;       // 4096
    const int tail     = n_tokens - ntiles * TOK;

    // 1024 CTAs -> each does exactly ntiles/1024 tiles (4 for 16384 tokens):
    // uniform work, persistent, pipelined.
    int grid = ntiles < 1024 ? (ntiles > 0 ? ntiles : 1) : 1024;

    if (ntiles > 0)
        embedding_dropout_pipe<<<grid, THREADS>>>(words, weight, mask, out, ntiles);
    if (tail > 0)
        embedding_dropout_k1<<<tail, THREADS>>>(words, weight, mask, out,
                                                ntiles * TOK, n_tokens);
}

// round 13
// speedup vs baseline: 1.0021x; 1.0021x over previous
#include <cuda_runtime.h>
#include <cuda_bf16.h>
#include <cstdint>

// out[t, :] = weight[words[t], :] * mask[words[t]]
// words: (16384,) int32, weight: (50257, 768) f32, mask: (50257,) f32
//
// R7: traffic-reduction round. Weight reads already hit L2 across graph
// replays; measured DRAM traffic (~47MB/replay) is output writeback. The
// full working set (41MB hot weight + 48MB output) fits in L2, so pin the
// OUTPUT stores with L2::evict_last -> dirty output lines stay resident and
// are overwritten in place next replay, suppressing writeback. Also drop
// front-batch depth 8 -> 4 (spread model: spr_max 2.0 -> 1.3) and recover
// occupancy. Thread c owns float4 column c of each row (fully coalesced).

static constexpr int DIM = 768;
static constexpr int VEC = 4;                 // float4
static constexpr int THREADS = DIM / VEC;     // 192
static constexpr int TOK_PER_CTA = 4;

__device__ __forceinline__ uint64_t make_evict_last_policy()
{
    uint64_t pol;
    asm("createpolicy.fractional.L2::evict_last.b64 %0, 1.0;" : "=l"(pol));
    return pol;
}

__device__ __forceinline__ void stg_el(float4* p, float4 v, uint64_t pol)
{
    asm volatile("st.global.L2::cache_hint.v4.f32 [%0], {%1,%2,%3,%4}, %5;"
                 :: "l"(p), "f"(v.x), "f"(v.y), "f"(v.z), "f"(v.w), "l"(pol)
                 : "memory");
}

__global__ __launch_bounds__(THREADS)
void embedding_dropout_k4(const int* __restrict__ words,
                          const float* __restrict__ weight,
                          const float* __restrict__ mask,
                          float* __restrict__ out)
{
    const uint64_t pol = make_evict_last_policy();
    const int c = threadIdx.x;

    // 4 token ids via one int4 load (uniform addr -> L1 broadcast).
    const int4 idx = __ldg(reinterpret_cast<const int4*>(words) + blockIdx.x);

    const size_t r0 = (size_t)idx.x * DIM, r1 = (size_t)idx.y * DIM;
    const size_t r2 = (size_t)idx.z * DIM, r3 = (size_t)idx.w * DIM;

    // Independent mask loads.
    const float m0 = __ldg(&mask[idx.x]), m1 = __ldg(&mask[idx.y]);
    const float m2 = __ldg(&mask[idx.z]), m3 = __ldg(&mask[idx.w]);

    // 4 independent LDG.128 gathers (MLP=4, spread-friendly).
    const float4 v0 = __ldg(reinterpret_cast<const float4*>(weight + r0) + c);
    const float4 v1 = __ldg(reinterpret_cast<const float4*>(weight + r1) + c);
    const float4 v2 = __ldg(reinterpret_cast<const float4*>(weight + r2) + c);
    const float4 v3 = __ldg(reinterpret_cast<const float4*>(weight + r3) + c);

    float4* dst = reinterpret_cast<float4*>(out)
                + (size_t)blockIdx.x * TOK_PER_CTA * THREADS + c;

    float4 s;
    s = v0; s.x *= m0; s.y *= m0; s.z *= m0; s.w *= m0; stg_el(dst + 0 * THREADS, s, pol);
    s = v1; s.x *= m1; s.y *= m1; s.z *= m1; s.w *= m1; stg_el(dst + 1 * THREADS, s, pol);
    s = v2; s.x *= m2; s.y *= m2; s.z *= m2; s.w *= m2; stg_el(dst + 2 * THREADS, s, pol);
    s = v3; s.x *= m3; s.y *= m3; s.z *= m3; s.w *= m3; stg_el(dst + 3 * THREADS, s, pol);
}

// Tail kernel: one token per CTA (only used if n_tokens % 4 != 0).
__global__ __launch_bounds__(THREADS)
void embedding_dropout_k1(const int* __restrict__ words,
                          const float* __restrict__ weight,
                          const float* __restrict__ mask,
                          float* __restrict__ out,
                          int t_base, int n_tokens)
{
    const uint64_t pol = make_evict_last_policy();
    const int t = t_base + blockIdx.x;
    if (t >= n_tokens) return;
    const int row = __ldg(&words[t]);
    const float m = __ldg(&mask[row]);
    const float4* src = reinterpret_cast<const float4*>(weight) + (size_t)row * THREADS;
    float4 v = __ldg(&src[threadIdx.x]);
    v.x *= m; v.y *= m; v.z *= m; v.w *= m;
    stg_el(reinterpret_cast<float4*>(out) + (size_t)t * THREADS + threadIdx.x, v, pol);
}

extern "C" void kernel_launch(void* const* d_in, const int* in_sizes, int n_in,
                              void* d_out, int out_size)
{
    const int*   words  = (const int*)d_in[0];
    const float* weight = (const float*)d_in[1];
    const float* mask   = (const float*)d_in[2];
    float*       out    = (float*)d_out;

    const int n_tokens = in_sizes[0];            // 16384
    const int n_full   = n_tokens / TOK_PER_CTA; // 4096
    const int tail     = n_tokens - n_full * TOK_PER_CTA;

    if (n_full > 0)
        embedding_dropout_k4<<<n_full, THREADS>>>(words, weight, mask, out);
    if (tail > 0)
        embedding_dropout_k1<<<tail, THREADS>>>(words, weight, mask, out,
                                                n_full * TOK_PER_CTA, n_tokens);
}

// round 15
// speedup vs baseline: 1.0043x; 1.0021x over previous
#include <cuda_runtime.h>
#include <cuda_bf16.h>
#include <cstdint>

// out[t, :] = weight[words[t], :] * mask[words[t]]
// words: (16384,) int32, weight: (50257, 768) f32, mask: (50257,) f32
//
// R8: TMA bulk-copy gather pipeline. Register-destination LDG gathers are
// latency-bound via the L1tex wavefront queue (all counters ~40%, issue 10%,
// robust 14-15us wall across every register-level variant). cp.async.bulk
// moves rows GMEM->SMEM with no register scoreboard and mbarrier
// complete_tx completion: thread 0 issues all 8 row copies up-front
// (2 stages x 4 rows x 3072B), consumers LDS+FMUL+STG per stage.

static constexpr int DIM      = 768;
static constexpr int ROWF4    = DIM / 4;        // 192 float4 per row
static constexpr int THREADS  = 192;            // 6 warps
static constexpr int TOK_STG  = 4;              // tokens per stage
static constexpr int STAGES   = 2;
static constexpr int TOK_CTA  = TOK_STG * STAGES;   // 8
static constexpr int ROW_BYTES   = DIM * 4;         // 3072
static constexpr int STAGE_BYTES = TOK_STG * ROW_BYTES;  // 12288

struct __align__(128) Smem {
    float    buf[STAGES][TOK_STG][DIM];   // 24 KB
    int      idx[TOK_CTA];
    unsigned long long mbar[STAGES];
};

__device__ __forceinline__ uint32_t smem_u32(const void* p)
{
    uint32_t a;
    asm("{ .reg .u64 t; cvta.to.shared.u64 t, %1; cvt.u32.u64 %0, t; }"
        : "=r"(a) : "l"(p));
    return a;
}

__device__ __forceinline__ void mbar_init(uint32_t mbar, uint32_t count)
{
    asm volatile("mbarrier.init.shared.b64 [%0], %1;" :: "r"(mbar), "r"(count) : "memory");
}

__device__ __forceinline__ void mbar_expect_tx(uint32_t mbar, uint32_t bytes)
{
    asm volatile("mbarrier.arrive.expect_tx.shared.b64 _, [%0], %1;"
                 :: "r"(mbar), "r"(bytes) : "memory");
}

__device__ __forceinline__ void bulk_g2s(uint32_t dst_smem, const void* src, uint32_t bytes,
                                         uint32_t mbar)
{
    asm volatile(
        "cp.async.bulk.shared::cluster.global.mbarrier::complete_tx::bytes "
        "[%0], [%1], %2, [%3];"
        :: "r"(dst_smem), "l"(src), "r"(bytes), "r"(mbar) : "memory");
}

__device__ __forceinline__ void mbar_wait(uint32_t mbar, uint32_t parity)
{
    uint32_t done;
    asm volatile(
        "{\n\t.reg .pred p;\n\t"
        "mbarrier.try_wait.parity.acquire.cta.shared::cta.b64 p, [%1], %2;\n\t"
        "selp.b32 %0, 1, 0, p;\n\t}"
        : "=r"(done) : "r"(mbar), "r"(parity) : "memory");
    if (!done) {
        asm volatile(
            "{\n\t.reg .pred P1;\n\t"
            "WAIT_LOOP_%=:\n\t"
            "mbarrier.try_wait.parity.acquire.cta.shared::cta.b64 P1, [%0], %1, 0x989680;\n\t"
            "@P1 bra.uni WAIT_DONE_%=;\n\t"
            "bra.uni WAIT_LOOP_%=;\n\t"
            "WAIT_DONE_%=:\n\t}"
            :: "r"(mbar), "r"(parity) : "memory");
    }
}

__global__ __launch_bounds__(THREADS)
void embedding_dropout_tma(const int* __restrict__ words,
                           const float* __restrict__ weight,
                           const float* __restrict__ mask,
                           float* __restrict__ out)
{
    __shared__ Smem sm;
    const int tid = threadIdx.x;
    const int t0  = blockIdx.x * TOK_CTA;

    if (tid == 0) {
        // 8 token ids
        const int4* wi = reinterpret_cast<const int4*>(words + t0);
        int4 a = __ldg(&wi[0]);
        int4 b = __ldg(&wi[1]);
        sm.idx[0] = a.x; sm.idx[1] = a.y; sm.idx[2] = a.z; sm.idx[3] = a.w;
        sm.idx[4] = b.x; sm.idx[5] = b.y; sm.idx[6] = b.z; sm.idx[7] = b.w;
        mbar_init(smem_u32(&sm.mbar[0]), 1);
        mbar_init(smem_u32(&sm.mbar[1]), 1);
    }
    __syncthreads();

    if (tid == 0) {
        // Issue both stages' row copies up-front: 8 x 3072B bulk copies.
#pragma unroll
        for (int s = 0; s < STAGES; ++s) {
            uint32_t mb = smem_u32(&sm.mbar[s]);
            mbar_expect_tx(mb, STAGE_BYTES);
#pragma unroll
            for (int j = 0; j < TOK_STG; ++j) {
                const float* src = weight + (size_t)sm.idx[s * TOK_STG + j] * DIM;
                bulk_g2s(smem_u32(&sm.buf[s][j][0]), src, ROW_BYTES, mb);
            }
        }
    }

    // All threads: fetch masks while TMA flies (independent scalar LDGs).
    float m[TOK_CTA];
#pragma unroll
    for (int k = 0; k < TOK_CTA; ++k)
        m[k] = __ldg(&mask[sm.idx[k]]);

    // Consume stages in order.
#pragma unroll
    for (int s = 0; s < STAGES; ++s) {
        mbar_wait(smem_u32(&sm.mbar[s]), 0);
#pragma unroll
        for (int j = 0; j < TOK_STG; ++j) {
            const int tok = s * TOK_STG + j;
            float4 v = reinterpret_cast<const float4*>(&sm.buf[s][j][0])[tid];
            const float mk = m[tok];
            v.x *= mk; v.y *= mk; v.z *= mk; v.w *= mk;
            reinterpret_cast<float4*>(out)[(size_t)(t0 + tok) * ROWF4 + tid] = v;
        }
    }
}

// Tail kernel: one token per CTA (only used if n_tokens % 8 != 0).
__global__ __launch_bounds__(THREADS)
void embedding_dropout_k1(const int* __restrict__ words,
                          const float* __restrict__ weight,
                          const float* __restrict__ mask,
                          float* __restrict__ out,
                          int t_base, int n_tokens)
{
    const int t = t_base + blockIdx.x;
    if (t >= n_tokens) return;
    const int row = __ldg(&words[t]);
    const float mk = __ldg(&mask[row]);
    const float4* src = reinterpret_cast<const float4*>(weight) + (size_t)row * ROWF4;
    float4 v = __ldg(&src[threadIdx.x]);
    v.x *= mk; v.y *= mk; v.z *= mk; v.w *= mk;
    reinterpret_cast<float4*>(out)[(size_t)t * ROWF4 + threadIdx.x] = v;
}

extern "C" void kernel_launch(void* const* d_in, const int* in_sizes, int n_in,
                              void* d_out, int out_size)
{
    const int*   words  = (const int*)d_in[0];
    const float* weight = (const float*)d_in[1];
    const float* mask   = (const float*)d_in[2];
    float*       out    = (float*)d_out;

    const int n_tokens = in_sizes[0];          // 16384
    const int n_full   = n_tokens / TOK_CTA;   // 2048
    const int tail     = n_tokens - n_full * TOK_CTA;

    if (n_full > 0)
        embedding_dropout_tma<<<n_full, THREADS>>>(words, weight, mask, out);
    if (tail > 0)
        embedding_dropout_k1<<<tail, THREADS>>>(words, weight, mask, out,
                                                n_full * TOK_CTA, n_tokens);
}